// round 1
// baseline (speedup 1.0000x reference)
#include <cuda_runtime.h>
#include <cuda_bf16.h>

#define NN 50000
#define NE 800000
#define FD 256

// ---------------- device scratch (no allocations allowed) ----------------
__device__ float g_dis[NN];        // degree, then deg^-1/2 in place
__device__ int   g_cnt[NN];        // edge count per row
__device__ int   g_off[NN];        // CSR row offsets (exclusive scan of cnt)
__device__ int   g_cur[NN];        // scatter cursors
__device__ int   g_col[NE];        // CSR col indices
__device__ float g_w[NE];          // CSR normalized weights
__device__ float g_y[(size_t)NN * FD]; // y = x @ W^T
__device__ int   g_is64;           // edge_index dtype flag

// ---------------- dtype detection for edge_index (int32 vs int64) --------
__global__ void k_detect(const int* ei32) {
    if (threadIdx.x == 0 && blockIdx.x == 0) {
        int odd_zero = 1;
        for (int i = 0; i < 128; i++) {
            if (ei32[2 * i + 1] != 0) { odd_zero = 0; break; }
        }
        g_is64 = odd_zero;
    }
}

__device__ __forceinline__ int edge_at(const void* ei, long long idx) {
    if (g_is64) return (int)((const long long*)ei)[idx];
    return ((const int*)ei)[idx];
}

// ---------------- init ----------------
__global__ void k_init() {
    int i = blockIdx.x * blockDim.x + threadIdx.x;
    if (i < NN) { g_dis[i] = 0.0f; g_cnt[i] = 0; }
}

// ---------------- degree accumulation ----------------
__global__ void k_deg(const void* __restrict__ ei, const float* __restrict__ C) {
    int e = blockIdx.x * blockDim.x + threadIdx.x;
    if (e < NE) {
        int r = edge_at(ei, e);
        atomicAdd(&g_dis[r], C[e]);
        atomicAdd(&g_cnt[r], 1);
    }
}

// ---------------- deg^-1/2 ----------------
__global__ void k_dis() {
    int i = blockIdx.x * blockDim.x + threadIdx.x;
    if (i < NN) {
        float d = g_dis[i];
        g_dis[i] = (d > 0.0f) ? rsqrtf(d) : 0.0f;
    }
}

// ---------------- single-block exclusive scan over 50000 counts ----------
__global__ void k_scan() {
    __shared__ int s[1024];
    const int t = threadIdx.x;
    const int CH = (NN + 1023) / 1024; // 49
    const int base = t * CH;
    int sum = 0;
    for (int i = 0; i < CH; i++) {
        int idx = base + i;
        if (idx < NN) sum += g_cnt[idx];
    }
    s[t] = sum;
    __syncthreads();
    // inclusive scan over the 1024 partials
    for (int off = 1; off < 1024; off <<= 1) {
        int v = (t >= off) ? s[t - off] : 0;
        __syncthreads();
        s[t] += v;
        __syncthreads();
    }
    int run = (t == 0) ? 0 : s[t - 1];
    for (int i = 0; i < CH; i++) {
        int idx = base + i;
        if (idx < NN) {
            g_off[idx] = run;
            g_cur[idx] = run;
            run += g_cnt[idx];
        }
    }
}

// ---------------- scatter edges into CSR + compute normalized weights ----
__global__ void k_scatter(const void* __restrict__ ei, const float* __restrict__ C) {
    int e = blockIdx.x * blockDim.x + threadIdx.x;
    if (e < NE) {
        int r  = edge_at(ei, e);
        int cl = edge_at(ei, (long long)NE + e);
        float w = g_dis[r] * C[e] * g_dis[cl];
        int p = atomicAdd(&g_cur[r], 1);
        g_col[p] = cl;
        g_w[p]   = w;
    }
}

// ---------------- GEMM: y[M,256] = x[M,256] @ W^T (W is 256x256, K-major both)
#define BM 128
#define BN 64
#define BK 16

__global__ __launch_bounds__(256) void k_gemm(const float* __restrict__ A,
                                              const float* __restrict__ B) {
    __shared__ float As[BK][BM];
    __shared__ float Bs[BK][BN];
    const int M = NN, K = FD;
    const int tid = threadIdx.x;
    const int bm = blockIdx.x, bn = blockIdx.y;
    const int ty = tid >> 4;   // 0..15
    const int tx = tid & 15;   // 0..15

    float acc[8][4];
#pragma unroll
    for (int i = 0; i < 8; i++)
#pragma unroll
        for (int j = 0; j < 4; j++) acc[i][j] = 0.0f;

    // A-tile load coords (2 float4 per thread): idx in [0,512)
    const int aRow0 = (tid * 2) >> 2;
    const int aKq0  = ((tid * 2) & 3) * 4;
    const int aRow1 = (tid * 2 + 1) >> 2;
    const int aKq1  = ((tid * 2 + 1) & 3) * 4;
    // B-tile load coords (1 float4 per thread): idx in [0,256)
    const int bN   = tid >> 2;
    const int bKq  = (tid & 3) * 4;

    const int gRow0 = bm * BM + aRow0;
    const int gRow1 = bm * BM + aRow1;
    const int gBrow = bn * BN + bN;

    float4 ra0, ra1, rb;
    // prologue: chunk 0
    ra0 = (gRow0 < M) ? *(const float4*)(A + (size_t)gRow0 * K + aKq0)
                      : make_float4(0.f, 0.f, 0.f, 0.f);
    ra1 = (gRow1 < M) ? *(const float4*)(A + (size_t)gRow1 * K + aKq1)
                      : make_float4(0.f, 0.f, 0.f, 0.f);
    rb  = *(const float4*)(B + (size_t)gBrow * K + bKq);

    As[aKq0 + 0][aRow0] = ra0.x; As[aKq0 + 1][aRow0] = ra0.y;
    As[aKq0 + 2][aRow0] = ra0.z; As[aKq0 + 3][aRow0] = ra0.w;
    As[aKq1 + 0][aRow1] = ra1.x; As[aKq1 + 1][aRow1] = ra1.y;
    As[aKq1 + 2][aRow1] = ra1.z; As[aKq1 + 3][aRow1] = ra1.w;
    Bs[bKq + 0][bN] = rb.x; Bs[bKq + 1][bN] = rb.y;
    Bs[bKq + 2][bN] = rb.z; Bs[bKq + 3][bN] = rb.w;
    __syncthreads();

    const int NCH = K / BK; // 16
    for (int c = 1; c <= NCH; c++) {
        if (c < NCH) {
            const int k0 = c * BK;
            ra0 = (gRow0 < M) ? *(const float4*)(A + (size_t)gRow0 * K + k0 + aKq0)
                              : make_float4(0.f, 0.f, 0.f, 0.f);
            ra1 = (gRow1 < M) ? *(const float4*)(A + (size_t)gRow1 * K + k0 + aKq1)
                              : make_float4(0.f, 0.f, 0.f, 0.f);
            rb  = *(const float4*)(B + (size_t)gBrow * K + k0 + bKq);
        }
#pragma unroll
        for (int kk = 0; kk < BK; kk++) {
            float4 av0 = *(const float4*)&As[kk][ty * 8];
            float4 av1 = *(const float4*)&As[kk][ty * 8 + 4];
            float4 bv  = *(const float4*)&Bs[kk][tx * 4];
            float a[8] = {av0.x, av0.y, av0.z, av0.w, av1.x, av1.y, av1.z, av1.w};
            float bb[4] = {bv.x, bv.y, bv.z, bv.w};
#pragma unroll
            for (int i = 0; i < 8; i++)
#pragma unroll
                for (int j = 0; j < 4; j++) acc[i][j] = fmaf(a[i], bb[j], acc[i][j]);
        }
        if (c < NCH) {
            __syncthreads();
            As[aKq0 + 0][aRow0] = ra0.x; As[aKq0 + 1][aRow0] = ra0.y;
            As[aKq0 + 2][aRow0] = ra0.z; As[aKq0 + 3][aRow0] = ra0.w;
            As[aKq1 + 0][aRow1] = ra1.x; As[aKq1 + 1][aRow1] = ra1.y;
            As[aKq1 + 2][aRow1] = ra1.z; As[aKq1 + 3][aRow1] = ra1.w;
            Bs[bKq + 0][bN] = rb.x; Bs[bKq + 1][bN] = rb.y;
            Bs[bKq + 2][bN] = rb.z; Bs[bKq + 3][bN] = rb.w;
            __syncthreads();
        }
    }

    // epilogue -> g_y
#pragma unroll
    for (int i = 0; i < 8; i++) {
        int grow = bm * BM + ty * 8 + i;
        if (grow < M) {
            float4 v = make_float4(acc[i][0], acc[i][1], acc[i][2], acc[i][3]);
            *(float4*)(g_y + (size_t)grow * FD + bn * BN + tx * 4) = v;
        }
    }
}

// ---------------- SpMM: out[i] = b + sum_e w[e] * y[col[e]]  (warp per row)
__global__ __launch_bounds__(256) void k_spmm(const float* __restrict__ bias,
                                              float* __restrict__ out) {
    int gwarp = (blockIdx.x * blockDim.x + threadIdx.x) >> 5;
    int lane  = threadIdx.x & 31;
    if (gwarp >= NN) return;

    const int beg = g_off[gwarp];
    const int end = beg + g_cnt[gwarp];

    const float4* b4 = (const float4*)bias;
    float4 acc0 = b4[lane * 2];
    float4 acc1 = b4[lane * 2 + 1];

    for (int p = beg; p < end; p++) {
        int   cl = g_col[p];
        float w  = g_w[p];
        const float4* yr = (const float4*)(g_y + (size_t)cl * FD);
        float4 v0 = yr[lane * 2];
        float4 v1 = yr[lane * 2 + 1];
        acc0.x = fmaf(w, v0.x, acc0.x);
        acc0.y = fmaf(w, v0.y, acc0.y);
        acc0.z = fmaf(w, v0.z, acc0.z);
        acc0.w = fmaf(w, v0.w, acc0.w);
        acc1.x = fmaf(w, v1.x, acc1.x);
        acc1.y = fmaf(w, v1.y, acc1.y);
        acc1.z = fmaf(w, v1.z, acc1.z);
        acc1.w = fmaf(w, v1.w, acc1.w);
    }

    float4* o = (float4*)(out + (size_t)gwarp * FD);
    o[lane * 2]     = acc0;
    o[lane * 2 + 1] = acc1;
}

// ---------------- launch ----------------
extern "C" void kernel_launch(void* const* d_in, const int* in_sizes, int n_in,
                              void* d_out, int out_size) {
    const float* x  = (const float*)d_in[0];
    const void*  ei = d_in[1];                 // int32 or int64, detected on device
    const float* C  = (const float*)d_in[2];
    const float* W  = (const float*)d_in[3];
    const float* b  = (const float*)d_in[4];
    float* out = (float*)d_out;

    k_detect<<<1, 32>>>((const int*)ei);
    k_init<<<(NN + 255) / 256, 256>>>();
    k_deg<<<(NE + 255) / 256, 256>>>(ei, C);
    k_dis<<<(NN + 255) / 256, 256>>>();
    k_scan<<<1, 1024>>>();
    k_scatter<<<(NE + 255) / 256, 256>>>(ei, C);

    dim3 gg((NN + BM - 1) / BM, FD / BN);
    k_gemm<<<gg, 256>>>(x, W);

    k_spmm<<<(NN * 32 + 255) / 256, 256>>>(b, out);
}

// round 2
// speedup vs baseline: 1.1895x; 1.1895x over previous
#include <cuda_runtime.h>
#include <cuda_bf16.h>
#include <mma.h>

using namespace nvcuda;

#define NN 50000
#define NNP 50048              // 391 * 128, padded for unguarded wmma stores
#define NE 800000
#define FD 256

// ---------------- device scratch (no allocations allowed) ----------------
__device__ float g_dis[NN];        // degree, then deg^-1/2 in place
__device__ int   g_cnt[NN];        // edge count per row
__device__ int   g_off[NN];        // CSR row offsets (exclusive scan of cnt)
__device__ int   g_cur[NN];        // scatter cursors
__device__ int   g_col[NE];        // CSR col indices
__device__ float g_w[NE];          // CSR normalized weights
__device__ float g_y[(size_t)NNP * FD]; // y = x @ W^T (padded rows)
__device__ int   g_is64;           // edge_index dtype flag

// ---------------- dtype detection for edge_index (int32 vs int64) --------
// If int64: for values < 50000, every odd 32-bit word is zero.
__global__ void k_detect(const int* ei32) {
    int t = threadIdx.x;                 // 128 threads
    int nz = (ei32[2 * t + 1] != 0) ? 1 : 0;
    int any = __syncthreads_or(nz);
    if (t == 0) g_is64 = (any == 0) ? 1 : 0;
}

__device__ __forceinline__ int edge_at(const void* ei, long long idx) {
    if (g_is64) return (int)((const long long*)ei)[idx];
    return ((const int*)ei)[idx];
}

// ---------------- init ----------------
__global__ void k_init() {
    int i = blockIdx.x * blockDim.x + threadIdx.x;
    if (i < NN) { g_dis[i] = 0.0f; g_cnt[i] = 0; }
}

// ---------------- degree accumulation ----------------
__global__ void k_deg(const void* __restrict__ ei, const float* __restrict__ C) {
    int e = blockIdx.x * blockDim.x + threadIdx.x;
    if (e < NE) {
        int r = edge_at(ei, e);
        atomicAdd(&g_dis[r], C[e]);
        atomicAdd(&g_cnt[r], 1);
    }
}

// ---------------- deg^-1/2 ----------------
__global__ void k_dis() {
    int i = blockIdx.x * blockDim.x + threadIdx.x;
    if (i < NN) {
        float d = g_dis[i];
        g_dis[i] = (d > 0.0f) ? rsqrtf(d) : 0.0f;
    }
}

// ---------------- single-block exclusive scan over 50000 counts ----------
__global__ void k_scan() {
    __shared__ int s[1024];
    const int t = threadIdx.x;
    const int CH = (NN + 1023) / 1024; // 49
    const int base = t * CH;
    int sum = 0;
    for (int i = 0; i < CH; i++) {
        int idx = base + i;
        if (idx < NN) sum += g_cnt[idx];
    }
    s[t] = sum;
    __syncthreads();
    for (int off = 1; off < 1024; off <<= 1) {
        int v = (t >= off) ? s[t - off] : 0;
        __syncthreads();
        s[t] += v;
        __syncthreads();
    }
    int run = (t == 0) ? 0 : s[t - 1];
    for (int i = 0; i < CH; i++) {
        int idx = base + i;
        if (idx < NN) {
            g_off[idx] = run;
            g_cur[idx] = run;
            run += g_cnt[idx];
        }
    }
}

// ---------------- scatter edges into CSR + compute normalized weights ----
__global__ void k_scatter(const void* __restrict__ ei, const float* __restrict__ C) {
    int e = blockIdx.x * blockDim.x + threadIdx.x;
    if (e < NE) {
        int r  = edge_at(ei, e);
        int cl = edge_at(ei, (long long)NE + e);
        float w = g_dis[r] * C[e] * g_dis[cl];
        int p = atomicAdd(&g_cur[r], 1);
        g_col[p] = cl;
        g_w[p]   = w;
    }
}

// ---------------- tf32 tensor-core GEMM: y[M,256] = x[M,256] @ W^T ------
// Block tile 128x64, K chunks of 32. 8 warps (4x2), each warp 32x32 via
// 2x2 wmma m16n16k8 tiles. Register-prefetch pipelined global->smem.
#define GM_BM 128
#define GM_BN 64
#define GM_BK 32
#define GM_BKP 36   // padded ld (floats); 36*4=144B, multiple of 16

__global__ __launch_bounds__(256) void k_gemm_tc(const float* __restrict__ A,
                                                 const float* __restrict__ B) {
    __shared__ __align__(16) float As[GM_BM][GM_BKP];
    __shared__ __align__(16) float Bs[GM_BN][GM_BKP];

    const int tid = threadIdx.x;
    const int w  = tid >> 5;
    const int wm = w & 3;      // 0..3 -> rows
    const int wn = w >> 2;     // 0..1 -> cols
    const int bm = blockIdx.x, bn = blockIdx.y;

    wmma::fragment<wmma::accumulator, 16, 16, 8, float> acc[2][2];
#pragma unroll
    for (int i = 0; i < 2; i++)
#pragma unroll
        for (int j = 0; j < 2; j++) wmma::fill_fragment(acc[i][j], 0.0f);

    // global load coordinates (float4 granularity; 8 float4 per k-row of 32)
    // A tile: 128x32 = 1024 float4 -> 4 per thread
    // B tile:  64x32 =  512 float4 -> 2 per thread
    int aR[4], aC[4], bR[2], bC[2];
#pragma unroll
    for (int i = 0; i < 4; i++) {
        int f = tid + 256 * i;
        aR[i] = f >> 3;
        aC[i] = (f & 7) * 4;
    }
#pragma unroll
    for (int i = 0; i < 2; i++) {
        int f = tid + 256 * i;
        bR[i] = f >> 3;
        bC[i] = (f & 7) * 4;
    }

    const float4 z4 = make_float4(0.f, 0.f, 0.f, 0.f);
    float4 ra[4], rb[2];

    // prologue: chunk 0
#pragma unroll
    for (int i = 0; i < 4; i++) {
        int gr = bm * GM_BM + aR[i];
        ra[i] = (gr < NN) ? *(const float4*)(A + (size_t)gr * FD + aC[i]) : z4;
    }
#pragma unroll
    for (int i = 0; i < 2; i++) {
        int gr = bn * GM_BN + bR[i];
        rb[i] = *(const float4*)(B + (size_t)gr * FD + bC[i]);
    }
#pragma unroll
    for (int i = 0; i < 4; i++) *(float4*)&As[aR[i]][aC[i]] = ra[i];
#pragma unroll
    for (int i = 0; i < 2; i++) *(float4*)&Bs[bR[i]][bC[i]] = rb[i];
    __syncthreads();

    const int NCH = FD / GM_BK; // 8
    for (int c = 1; c <= NCH; c++) {
        if (c < NCH) {
            const int k0 = c * GM_BK;
#pragma unroll
            for (int i = 0; i < 4; i++) {
                int gr = bm * GM_BM + aR[i];
                ra[i] = (gr < NN) ? *(const float4*)(A + (size_t)gr * FD + k0 + aC[i]) : z4;
            }
#pragma unroll
            for (int i = 0; i < 2; i++) {
                int gr = bn * GM_BN + bR[i];
                rb[i] = *(const float4*)(B + (size_t)gr * FD + k0 + bC[i]);
            }
        }

        // compute: 4 k-steps of 8
#pragma unroll
        for (int ks = 0; ks < 4; ks++) {
            const int k0 = ks * 8;
            wmma::fragment<wmma::matrix_a, 16, 16, 8, wmma::precision::tf32, wmma::row_major> af[2];
            wmma::fragment<wmma::matrix_b, 16, 16, 8, wmma::precision::tf32, wmma::col_major> bf[2];
            wmma::load_matrix_sync(af[0], &As[wm * 32 +  0][k0], GM_BKP);
            wmma::load_matrix_sync(af[1], &As[wm * 32 + 16][k0], GM_BKP);
            wmma::load_matrix_sync(bf[0], &Bs[wn * 32 +  0][k0], GM_BKP);
            wmma::load_matrix_sync(bf[1], &Bs[wn * 32 + 16][k0], GM_BKP);
#pragma unroll
            for (int t = 0; t < af[0].num_elements; t++) {
                af[0].x[t] = wmma::__float_to_tf32(af[0].x[t]);
                af[1].x[t] = wmma::__float_to_tf32(af[1].x[t]);
            }
#pragma unroll
            for (int t = 0; t < bf[0].num_elements; t++) {
                bf[0].x[t] = wmma::__float_to_tf32(bf[0].x[t]);
                bf[1].x[t] = wmma::__float_to_tf32(bf[1].x[t]);
            }
#pragma unroll
            for (int i = 0; i < 2; i++)
#pragma unroll
                for (int j = 0; j < 2; j++)
                    wmma::mma_sync(acc[i][j], af[i], bf[j], acc[i][j]);
        }

        if (c < NCH) {
            __syncthreads();
#pragma unroll
            for (int i = 0; i < 4; i++) *(float4*)&As[aR[i]][aC[i]] = ra[i];
#pragma unroll
            for (int i = 0; i < 2; i++) *(float4*)&Bs[bR[i]][bC[i]] = rb[i];
            __syncthreads();
        }
    }

    // epilogue: unguarded stores into padded g_y (NNP rows)
#pragma unroll
    for (int i = 0; i < 2; i++) {
        int gr = bm * GM_BM + wm * 32 + i * 16;
#pragma unroll
        for (int j = 0; j < 2; j++) {
            int gc = bn * GM_BN + wn * 32 + j * 16;
            wmma::store_matrix_sync(g_y + (size_t)gr * FD + gc, acc[i][j], FD,
                                    wmma::mem_row_major);
        }
    }
}

// ---------------- SpMM: out[i] = b + sum_e w[e] * y[col[e]]  (warp per row)
__global__ __launch_bounds__(256) void k_spmm(const float* __restrict__ bias,
                                              float* __restrict__ out) {
    int gwarp = (blockIdx.x * blockDim.x + threadIdx.x) >> 5;
    int lane  = threadIdx.x & 31;
    if (gwarp >= NN) return;

    const int beg = g_off[gwarp];
    const int end = beg + g_cnt[gwarp];

    const float4* b4 = (const float4*)bias;
    float4 acc0 = b4[lane * 2];
    float4 acc1 = b4[lane * 2 + 1];

    int p = beg;
    for (; p + 1 < end; p += 2) {
        int   c0 = g_col[p],   c1 = g_col[p + 1];
        float w0 = g_w[p],     w1 = g_w[p + 1];
        const float4* y0 = (const float4*)(g_y + (size_t)c0 * FD);
        const float4* y1 = (const float4*)(g_y + (size_t)c1 * FD);
        float4 u0 = y0[lane * 2], u1 = y0[lane * 2 + 1];
        float4 v0 = y1[lane * 2], v1 = y1[lane * 2 + 1];
        acc0.x = fmaf(w0, u0.x, acc0.x); acc0.y = fmaf(w0, u0.y, acc0.y);
        acc0.z = fmaf(w0, u0.z, acc0.z); acc0.w = fmaf(w0, u0.w, acc0.w);
        acc1.x = fmaf(w0, u1.x, acc1.x); acc1.y = fmaf(w0, u1.y, acc1.y);
        acc1.z = fmaf(w0, u1.z, acc1.z); acc1.w = fmaf(w0, u1.w, acc1.w);
        acc0.x = fmaf(w1, v0.x, acc0.x); acc0.y = fmaf(w1, v0.y, acc0.y);
        acc0.z = fmaf(w1, v0.z, acc0.z); acc0.w = fmaf(w1, v0.w, acc0.w);
        acc1.x = fmaf(w1, v1.x, acc1.x); acc1.y = fmaf(w1, v1.y, acc1.y);
        acc1.z = fmaf(w1, v1.z, acc1.z); acc1.w = fmaf(w1, v1.w, acc1.w);
    }
    if (p < end) {
        int   cl = g_col[p];
        float wv = g_w[p];
        const float4* yr = (const float4*)(g_y + (size_t)cl * FD);
        float4 u0 = yr[lane * 2], u1 = yr[lane * 2 + 1];
        acc0.x = fmaf(wv, u0.x, acc0.x); acc0.y = fmaf(wv, u0.y, acc0.y);
        acc0.z = fmaf(wv, u0.z, acc0.z); acc0.w = fmaf(wv, u0.w, acc0.w);
        acc1.x = fmaf(wv, u1.x, acc1.x); acc1.y = fmaf(wv, u1.y, acc1.y);
        acc1.z = fmaf(wv, u1.z, acc1.z); acc1.w = fmaf(wv, u1.w, acc1.w);
    }

    float4* o = (float4*)(out + (size_t)gwarp * FD);
    o[lane * 2]     = acc0;
    o[lane * 2 + 1] = acc1;
}

// ---------------- launch ----------------
extern "C" void kernel_launch(void* const* d_in, const int* in_sizes, int n_in,
                              void* d_out, int out_size) {
    const float* x  = (const float*)d_in[0];
    const void*  ei = d_in[1];                 // int32 or int64, detected on device
    const float* C  = (const float*)d_in[2];
    const float* W  = (const float*)d_in[3];
    const float* b  = (const float*)d_in[4];
    float* out = (float*)d_out;

    k_detect<<<1, 128>>>((const int*)ei);
    k_init<<<(NN + 255) / 256, 256>>>();
    k_deg<<<(NE + 255) / 256, 256>>>(ei, C);
    k_dis<<<(NN + 255) / 256, 256>>>();
    k_scan<<<1, 1024>>>();
    k_scatter<<<(NE + 255) / 256, 256>>>(ei, C);

    dim3 gg((NN + GM_BM - 1) / GM_BM, FD / GM_BN);
    k_gemm_tc<<<gg, 256>>>(x, W);

    k_spmm<<<(NN * 32 + 255) / 256, 256>>>(b, out);
}